// round 7
// baseline (speedup 1.0000x reference)
#include <cuda_runtime.h>
#include <cuda_bf16.h>

#define R_MAX 2.0f
#define DR_MIN 0.02f
#define PI_F 3.14159265358979323846f
#define NBLOCKS 148
#define NTHREADS 896

__device__ unsigned char g_Z8[204800];
__device__ float g_partials[NBLOCKS];
__device__ unsigned int g_count = 0;

__global__ void z_to_u8_kernel(const int* __restrict__ Z, int n)
{
    int i = blockIdx.x * blockDim.x + threadIdx.x;
    int n4 = n >> 2;
    if (i < n4) {
        int4 z = __ldg((const int4*)Z + i);
        ((uchar4*)g_Z8)[i] = make_uchar4((unsigned char)z.x, (unsigned char)z.y,
                                         (unsigned char)z.z, (unsigned char)z.w);
    }
    if (i == 0) {
        for (int k = n4 << 2; k < n; k++) g_Z8[k] = (unsigned char)Z[k];
    }
}

__device__ __forceinline__ float4 shfl_f4(float4 v, int src) {
    float4 r;
    r.x = __shfl_sync(0xFFFFFFFF, v.x, src);
    r.y = __shfl_sync(0xFFFFFFFF, v.y, src);
    r.z = __shfl_sync(0xFFFFFFFF, v.z, src);
    r.w = __shfl_sync(0xFFFFFFFF, v.w, src);
    return r;
}

__global__ void __launch_bounds__(NTHREADS, 1)
exp_rep_kernel(const float* __restrict__ dr_vec,
               const int* __restrict__ idx_i,
               const int* __restrict__ idx_j,
               const float* __restrict__ rep_scale,
               const float* __restrict__ rep_prefactor,
               float* __restrict__ out,
               int n_edges, int n_atoms)
{
    extern __shared__ unsigned char smem[];
    float2* s_tab = (float2*)smem;              // 119 x {|A|, 1/|R|}
    unsigned char* s_Z = smem + 1024;           // n_atoms bytes (uint8 Z)

    int tid = threadIdx.x;
    int lane = tid & 31;
    if (tid < 119) {
        s_tab[tid] = make_float2(fabsf(rep_prefactor[tid]),
                                 1.0f / fabsf(rep_scale[tid]));
    }
    // stage u8 Z -> smem (16B chunks)
    int n16 = n_atoms >> 4;
    const int4* gZ16 = (const int4*)g_Z8;
    int4* sZ16 = (int4*)s_Z;
    for (int i = tid; i < n16; i += NTHREADS)
        sZ16[i] = __ldg(gZ16 + i);
    for (int i = (n16 << 4) + tid; i < n_atoms; i += NTHREADS)
        s_Z[i] = g_Z8[i];
    __syncthreads();

    // shuffle-transpose selectors (loop-invariant):
    // round w: lane L reads float4 #(3L+w) from lane (3L+w)&31;
    // source lane S must expose reg floor(k/32), k = 3*((S-w)*11 mod 32) + w
    int sl0 = (3 * lane + 0) & 31;
    int sl1 = (3 * lane + 1) & 31;
    int sl2 = (3 * lane + 2) & 31;
    int rs0 = (3 * (((lane - 0) * 11) & 31) + 0) >> 5;
    int rs1 = (3 * (((lane - 1) * 11) & 31) + 1) >> 5;
    int rs2 = (3 * (((lane - 2) * 11) & 31) + 2) >> 5;

    float acc = 0.0f;
    int n_chunks = n_edges >> 2;
    int gstride = NBLOCKS * NTHREADS;
    const float4* dv4 = (const float4*)dr_vec;
    const int4*   I4  = (const int4*)idx_i;
    const int4*   J4  = (const int4*)idx_j;

    // ---- pipelined loop, warp-uniform trip count ----
    int c = blockIdx.x * NTHREADS + tid;     // (c & 31) == lane
    bool wvalid = (c & ~31) < n_chunks;      // warp-uniform
    float4 A, B, C;
    int4 ii4, jj4;
    bool fast = false;
    A = B = C = make_float4(0.f, 0.f, 0.f, 0.f);
    ii4 = jj4 = make_int4(0, 0, 0, 0);
    if (wvalid) {
        fast = ((c | 31) < n_chunks);
        if (fast) {
            int fb = 3 * (c & ~31);
            A = __ldcs(dv4 + fb + lane);
            B = __ldcs(dv4 + fb + 32 + lane);
            C = __ldcs(dv4 + fb + 64 + lane);
            ii4 = __ldcs(I4 + c);
            jj4 = __ldcs(J4 + c);
        } else if (c < n_chunks) {
            A = __ldcs(dv4 + 3 * c + 0);
            B = __ldcs(dv4 + 3 * c + 1);
            C = __ldcs(dv4 + 3 * c + 2);
            ii4 = __ldcs(I4 + c);
            jj4 = __ldcs(J4 + c);
        }
    }

    while (wvalid) {
        // prefetch next
        int cn = c + gstride;
        bool nwvalid = (cn & ~31) < n_chunks;
        bool nfast = false;
        float4 nA = A, nB = B, nC = C;
        int4 nii = ii4, njj = jj4;
        if (nwvalid) {
            nfast = ((cn | 31) < n_chunks);
            if (nfast) {
                int fb = 3 * (cn & ~31);
                nA = __ldcs(dv4 + fb + lane);
                nB = __ldcs(dv4 + fb + 32 + lane);
                nC = __ldcs(dv4 + fb + 64 + lane);
                nii = __ldcs(I4 + cn);
                njj = __ldcs(J4 + cn);
            } else if (cn < n_chunks) {
                nA = __ldcs(dv4 + 3 * cn + 0);
                nB = __ldcs(dv4 + 3 * cn + 1);
                nC = __ldcs(dv4 + 3 * cn + 2);
                nii = __ldcs(I4 + cn);
                njj = __ldcs(J4 + cn);
            }
        }

        // ---- compute current chunk ----
        bool lvalid = (c < n_chunks);
        float4 va, vb, vc;
        if (fast) {
            float4 e0 = (rs0 == 0) ? A : ((rs0 == 1) ? B : C);
            float4 e1 = (rs1 == 0) ? A : ((rs1 == 1) ? B : C);
            float4 e2 = (rs2 == 0) ? A : ((rs2 == 1) ? B : C);
            va = shfl_f4(e0, sl0);
            vb = shfl_f4(e1, sl1);
            vc = shfl_f4(e2, sl2);
        } else {
            va = A; vb = B; vc = C;
        }

        if (lvalid) {
            float ex[4], ey[4], ez[4];
            ex[0] = va.x; ey[0] = va.y; ez[0] = va.z;
            ex[1] = va.w; ey[1] = vb.x; ez[1] = vb.y;
            ex[2] = vb.z; ey[2] = vb.w; ez[2] = vc.x;
            ex[3] = vc.y; ey[3] = vc.z; ez[3] = vc.w;
            int ii[4] = {ii4.x, ii4.y, ii4.z, ii4.w};
            int jj[4] = {jj4.x, jj4.y, jj4.z, jj4.w};

            int zi[4], zj[4];
            #pragma unroll
            for (int k = 0; k < 4; k++) {
                zi[k] = (int)s_Z[ii[k]];
                zj[k] = (int)s_Z[jj[k]];
            }
            float2 pi[4], pj[4];
            #pragma unroll
            for (int k = 0; k < 4; k++) {
                pi[k] = s_tab[zi[k]];
                pj[k] = s_tab[zj[k]];
            }

            #pragma unroll
            for (int k = 0; k < 4; k++) {
                float r2 = ex[k]*ex[k] + ey[k]*ey[k] + ez[k]*ez[k];
                float dr = sqrtf(r2);
                dr = fminf(fmaxf(dr, DR_MIN), R_MAX);
                float cosc = 0.5f * (__cosf(dr * (PI_F / R_MAX)) + 1.0f);
                float f = pi[k].x * pj[k].x * __expf(-dr * (pi[k].y + pj[k].y)) *
                          __fdividef(cosc, dr * dr);
                acc += (ii[k] != jj[k]) ? f : 0.0f;
            }
        }

        // rotate
        c = cn; wvalid = nwvalid; fast = nfast;
        A = nA; B = nB; C = nC;
        ii4 = nii; jj4 = njj;
    }

    // remainder edges (n_edges % 4): block 0, thread 0
    if (blockIdx.x == 0 && tid == 0) {
        int n_chunks_l = n_edges >> 2;
        for (int e = n_chunks_l << 2; e < n_edges; e++) {
            float dx = dr_vec[3*e+0], dy = dr_vec[3*e+1], dz = dr_vec[3*e+2];
            int ii = idx_i[e], jj = idx_j[e];
            float2 pi = s_tab[(int)s_Z[ii]];
            float2 pj = s_tab[(int)s_Z[jj]];
            float dr = sqrtf(dx*dx + dy*dy + dz*dz);
            dr = fminf(fmaxf(dr, DR_MIN), R_MAX);
            float cosc = 0.5f * (__cosf(dr * (PI_F / R_MAX)) + 1.0f);
            float f = pi.x * pj.x * __expf(-dr * (pi.y + pj.y)) *
                      __fdividef(cosc, dr * dr);
            acc += (ii != jj) ? f : 0.0f;
        }
    }

    // warp reduce, block reduce, deterministic cross-block finish
    #pragma unroll
    for (int off = 16; off > 0; off >>= 1)
        acc += __shfl_down_sync(0xFFFFFFFF, acc, off);

    __shared__ float s_red[32];
    int warp = tid >> 5;
    if (lane == 0) s_red[warp] = acc;
    __syncthreads();
    if (warp == 0) {
        float v = (tid < (NTHREADS / 32)) ? s_red[tid] : 0.0f;
        #pragma unroll
        for (int off = 16; off > 0; off >>= 1)
            v += __shfl_down_sync(0xFFFFFFFF, v, off);
        if (tid == 0) {
            g_partials[blockIdx.x] = v;
            __threadfence();
            unsigned int ticket = atomicAdd(&g_count, 1u);
            if (ticket == NBLOCKS - 1) {
                float s = 0.0f;
                #pragma unroll 4
                for (int i = 0; i < NBLOCKS; i++) s += g_partials[i];
                out[0] = s;
                g_count = 0;  // reset for next graph replay
            }
        }
    }
}

extern "C" void kernel_launch(void* const* d_in, const int* in_sizes, int n_in,
                              void* d_out, int out_size)
{
    const float* dr_vec        = (const float*)d_in[1];
    const int*   Z             = (const int*)d_in[2];
    const int*   idx           = (const int*)d_in[3];
    const float* rep_scale     = (const float*)d_in[6];
    const float* rep_prefactor = (const float*)d_in[7];
    float* out = (float*)d_out;

    int n_edges = in_sizes[1] / 3;
    int n_atoms = in_sizes[2];
    const int* idx_i = idx;
    const int* idx_j = idx + n_edges;

    int n4 = n_atoms >> 2;
    z_to_u8_kernel<<<(n4 + 255) / 256, 256>>>(Z, n_atoms);

    int smem_bytes = 1024 + ((n_atoms + 15) & ~15);
    cudaFuncSetAttribute(exp_rep_kernel,
                         cudaFuncAttributeMaxDynamicSharedMemorySize, smem_bytes);

    exp_rep_kernel<<<NBLOCKS, NTHREADS, smem_bytes>>>(
        dr_vec, idx_i, idx_j, rep_scale, rep_prefactor,
        out, n_edges, n_atoms);
}

// round 8
// speedup vs baseline: 1.0653x; 1.0653x over previous
#include <cuda_runtime.h>
#include <cuda_bf16.h>

#define R_MAX 2.0f
#define DR_MIN 0.02f
#define PI_F 3.14159265358979323846f
#define NBLOCKS 148
#define NTHREADS 768

__device__ unsigned char g_Z8[204800];
__device__ float g_partials[NBLOCKS];
__device__ unsigned int g_count = 0;

__global__ void z_to_u8_kernel(const int* __restrict__ Z, int n)
{
    int i = blockIdx.x * blockDim.x + threadIdx.x;
    int n4 = n >> 2;
    if (i < n4) {
        int4 z = __ldg((const int4*)Z + i);
        ((uchar4*)g_Z8)[i] = make_uchar4((unsigned char)z.x, (unsigned char)z.y,
                                         (unsigned char)z.z, (unsigned char)z.w);
    }
    if (i == 0) {
        for (int k = n4 << 2; k < n; k++) g_Z8[k] = (unsigned char)Z[k];
    }
}

// smem layout: 4 replicated tables (stride 129 float2 = 1032B -> +2 bank shift
// per copy), then the u8 Z array.
#define TAB_STRIDE 129
#define TAB_BYTES 4224   // 4*129*8 = 4128, rounded to 16

__global__ void __launch_bounds__(NTHREADS, 1)
exp_rep_kernel(const float* __restrict__ dr_vec,
               const int* __restrict__ idx_i,
               const int* __restrict__ idx_j,
               const float* __restrict__ rep_scale,
               const float* __restrict__ rep_prefactor,
               float* __restrict__ out,
               int n_edges, int n_atoms)
{
    extern __shared__ unsigned char smem[];
    float2* s_tab = (float2*)smem;                 // 4 copies, stride TAB_STRIDE
    unsigned char* s_Z = smem + TAB_BYTES;         // n_atoms bytes

    int tid = threadIdx.x;
    int lane = tid & 31;
    if (tid < 119) {
        float2 v = make_float2(fabsf(rep_prefactor[tid]),
                               1.0f / fabsf(rep_scale[tid]));
        #pragma unroll
        for (int cp = 0; cp < 4; cp++)
            s_tab[cp * TAB_STRIDE + tid] = v;
    }
    // stage u8 Z -> smem (16B chunks)
    int n16 = n_atoms >> 4;
    const int4* gZ16 = (const int4*)g_Z8;
    int4* sZ16 = (int4*)s_Z;
    for (int i = tid; i < n16; i += NTHREADS)
        sZ16[i] = __ldg(gZ16 + i);
    for (int i = (n16 << 4) + tid; i < n_atoms; i += NTHREADS)
        s_Z[i] = g_Z8[i];
    __syncthreads();

    const float2* my_tab = s_tab + (lane & 3) * TAB_STRIDE;

    float acc = 0.0f;
    int n_chunks = n_edges >> 2;
    int s = NBLOCKS * NTHREADS;
    const float4* dv4 = (const float4*)dr_vec;
    const int4*   I4  = (const int4*)idx_i;
    const int4*   J4  = (const int4*)idx_j;

    // ---- pipeline: idx prefetched 2 deep, dr_vec 1 deep ----
    int c = blockIdx.x * NTHREADS + tid;
    bool vA = (c < n_chunks);
    bool vB = (c + s < n_chunks);
    int4 iiA, jjA, iiB, jjB;
    float4 va, vb, vc;
    iiA = jjA = iiB = jjB = make_int4(0, 0, 0, 0);
    va = vb = vc = make_float4(0.f, 0.f, 0.f, 0.f);
    if (vA) {
        iiA = __ldcs(I4 + c);
        jjA = __ldcs(J4 + c);
        va  = __ldcs(dv4 + 3 * c + 0);
        vb  = __ldcs(dv4 + 3 * c + 1);
        vc  = __ldcs(dv4 + 3 * c + 2);
    }
    if (vB) {
        iiB = __ldcs(I4 + c + s);
        jjB = __ldcs(J4 + c + s);
    }

    while (vA) {
        int c1 = c + s;
        int c2 = c + 2 * s;
        bool v1 = vB;
        bool v2 = (c2 < n_chunks);

        // prefetch: dr for c1, idx for c2
        float4 nva = va, nvb = vb, nvc = vc;
        int4 nii = iiA, njj = jjA;
        if (v1) {
            nva = __ldcs(dv4 + 3 * c1 + 0);
            nvb = __ldcs(dv4 + 3 * c1 + 1);
            nvc = __ldcs(dv4 + 3 * c1 + 2);
        }
        if (v2) {
            nii = __ldcs(I4 + c2);
            njj = __ldcs(J4 + c2);
        }

        // ---- compute chunk c (idx arrived 2 iters ago, dr 1 iter ago) ----
        float ex[4], ey[4], ez[4];
        ex[0] = va.x; ey[0] = va.y; ez[0] = va.z;
        ex[1] = va.w; ey[1] = vb.x; ez[1] = vb.y;
        ex[2] = vb.z; ey[2] = vb.w; ez[2] = vc.x;
        ex[3] = vc.y; ey[3] = vc.z; ez[3] = vc.w;
        int ii[4] = {iiA.x, iiA.y, iiA.z, iiA.w};
        int jj[4] = {jjA.x, jjA.y, jjA.z, jjA.w};

        int zi[4], zj[4];
        #pragma unroll
        for (int k = 0; k < 4; k++) {
            zi[k] = (int)s_Z[ii[k]];
            zj[k] = (int)s_Z[jj[k]];
        }
        float2 pi[4], pj[4];
        #pragma unroll
        for (int k = 0; k < 4; k++) {
            pi[k] = my_tab[zi[k]];
            pj[k] = my_tab[zj[k]];
        }

        #pragma unroll
        for (int k = 0; k < 4; k++) {
            float r2 = ex[k]*ex[k] + ey[k]*ey[k] + ez[k]*ez[k];
            float dr = sqrtf(r2);
            dr = fminf(fmaxf(dr, DR_MIN), R_MAX);
            float cosc = 0.5f * (__cosf(dr * (PI_F / R_MAX)) + 1.0f);
            float f = pi[k].x * pj[k].x * __expf(-dr * (pi[k].y + pj[k].y)) *
                      __fdividef(cosc, dr * dr);
            acc += (ii[k] != jj[k]) ? f : 0.0f;
        }

        // rotate pipeline
        c = c1; vA = v1; vB = v2;
        iiA = iiB; jjA = jjB;
        iiB = nii; jjB = njj;
        va = nva; vb = nvb; vc = nvc;
    }

    // remainder edges (n_edges % 4): block 0, thread 0
    if (blockIdx.x == 0 && tid == 0) {
        for (int e = n_chunks << 2; e < n_edges; e++) {
            float dx = dr_vec[3*e+0], dy = dr_vec[3*e+1], dz = dr_vec[3*e+2];
            int ii = idx_i[e], jj = idx_j[e];
            float2 pi = my_tab[(int)s_Z[ii]];
            float2 pj = my_tab[(int)s_Z[jj]];
            float dr = sqrtf(dx*dx + dy*dy + dz*dz);
            dr = fminf(fmaxf(dr, DR_MIN), R_MAX);
            float cosc = 0.5f * (__cosf(dr * (PI_F / R_MAX)) + 1.0f);
            float f = pi.x * pj.x * __expf(-dr * (pi.y + pj.y)) *
                      __fdividef(cosc, dr * dr);
            acc += (ii != jj) ? f : 0.0f;
        }
    }

    // warp reduce, block reduce, deterministic cross-block finish
    #pragma unroll
    for (int off = 16; off > 0; off >>= 1)
        acc += __shfl_down_sync(0xFFFFFFFF, acc, off);

    __shared__ float s_red[32];
    int warp = tid >> 5;
    if (lane == 0) s_red[warp] = acc;
    __syncthreads();
    if (warp == 0) {
        float v = (tid < (NTHREADS / 32)) ? s_red[tid] : 0.0f;
        #pragma unroll
        for (int off = 16; off > 0; off >>= 1)
            v += __shfl_down_sync(0xFFFFFFFF, v, off);
        if (tid == 0) {
            g_partials[blockIdx.x] = v;
            __threadfence();
            unsigned int ticket = atomicAdd(&g_count, 1u);
            if (ticket == NBLOCKS - 1) {
                float sum = 0.0f;
                #pragma unroll 4
                for (int i = 0; i < NBLOCKS; i++) sum += g_partials[i];
                out[0] = sum;
                g_count = 0;  // reset for next graph replay
            }
        }
    }
}

extern "C" void kernel_launch(void* const* d_in, const int* in_sizes, int n_in,
                              void* d_out, int out_size)
{
    const float* dr_vec        = (const float*)d_in[1];
    const int*   Z             = (const int*)d_in[2];
    const int*   idx           = (const int*)d_in[3];
    const float* rep_scale     = (const float*)d_in[6];
    const float* rep_prefactor = (const float*)d_in[7];
    float* out = (float*)d_out;

    int n_edges = in_sizes[1] / 3;
    int n_atoms = in_sizes[2];
    const int* idx_i = idx;
    const int* idx_j = idx + n_edges;

    int n4 = n_atoms >> 2;
    z_to_u8_kernel<<<(n4 + 255) / 256, 256>>>(Z, n_atoms);

    int smem_bytes = TAB_BYTES + ((n_atoms + 15) & ~15);
    cudaFuncSetAttribute(exp_rep_kernel,
                         cudaFuncAttributeMaxDynamicSharedMemorySize, smem_bytes);

    exp_rep_kernel<<<NBLOCKS, NTHREADS, smem_bytes>>>(
        dr_vec, idx_i, idx_j, rep_scale, rep_prefactor,
        out, n_edges, n_atoms);
}